// round 1
// baseline (speedup 1.0000x reference)
#include <cuda_runtime.h>
#include <math.h>

#define B_    256
#define D_    1024
#define N_    65536
#define C_    8192
#define TEMP_ 0.05f
#define TOPP_ 0.1f
#define EPS_  1e-6f

// -------- scratch (device globals: no allocation allowed) --------
__device__ float g_inputs[B_ * D_];          // normalized inputs   (1 MB)
__device__ float g_Fagg[(size_t)C_ * D_];    // per-cluster mean / TEMP (32 MB)
__device__ int   g_counts[C_];
__device__ int   g_offsets[C_];
__device__ int   g_cursor[C_];
__device__ int   g_order[N_];
__device__ float g_sim[(size_t)B_ * C_];     // logits (8 MB)
__device__ float g_loss[B_];

// -------- packed f32x2 helpers (FFMA2) --------
__device__ __forceinline__ unsigned long long pack2(float x, float y) {
    unsigned long long r;
    asm("mov.b64 %0, {%1, %2};" : "=l"(r) : "f"(x), "f"(y));
    return r;
}
__device__ __forceinline__ void fma2(unsigned long long& d, unsigned long long a,
                                     unsigned long long b) {
    asm("fma.rn.f32x2 %0, %1, %2, %0;" : "+l"(d) : "l"(a), "l"(b));
}

// -------- 1) L2-normalize the query rows --------
__global__ void k_norm(const float* __restrict__ res) {
    __shared__ float red[256];
    int b = blockIdx.x, t = threadIdx.x;
    const float* row = res + (size_t)b * D_;
    float s = 0.f;
    for (int i = t; i < D_; i += 256) { float v = row[i]; s += v * v; }
    red[t] = s; __syncthreads();
    for (int o = 128; o > 0; o >>= 1) { if (t < o) red[t] += red[t + o]; __syncthreads(); }
    float inv = rsqrtf(red[0]);
    for (int i = t; i < D_; i += 256) g_inputs[(size_t)b * D_ + i] = row[i] * inv;
}

// -------- 2) histogram of labels --------
__global__ void k_zero() {
    int i = blockIdx.x * blockDim.x + threadIdx.x;
    if (i < C_) g_counts[i] = 0;
}
__global__ void k_hist(const int* __restrict__ labels) {
    int n = blockIdx.x * blockDim.x + threadIdx.x;
    if (n < N_) atomicAdd(&g_counts[labels[n]], 1);
}

// -------- 3) exclusive scan of counts (1 block, 1024 threads x 8) --------
__global__ void k_scan() {
    __shared__ int s[1024];
    int t = threadIdx.x;
    int base = t * 8;
    int v[8]; int tot = 0;
#pragma unroll
    for (int i = 0; i < 8; i++) { v[i] = g_counts[base + i]; tot += v[i]; }
    s[t] = tot; __syncthreads();
    for (int o = 1; o < 1024; o <<= 1) {
        int x = (t >= o) ? s[t - o] : 0;
        __syncthreads();
        s[t] += x;
        __syncthreads();
    }
    int excl = s[t] - tot;
#pragma unroll
    for (int i = 0; i < 8; i++) {
        g_offsets[base + i] = excl;
        g_cursor[base + i]  = excl;
        excl += v[i];
    }
}

// -------- 4) counting-sort scatter --------
__global__ void k_scatter(const int* __restrict__ labels) {
    int n = blockIdx.x * blockDim.x + threadIdx.x;
    if (n < N_) {
        int l = labels[n];
        int p = atomicAdd(&g_cursor[l], 1);
        g_order[p] = n;
    }
}

// -------- 5) per-cluster feature aggregation: F_agg[c] = sum/(TEMP*cnt) --------
__global__ void k_agg(const float* __restrict__ feat) {
    __shared__ int idxs[64];
    int c = blockIdx.x, t = threadIdx.x;
    int cnt = g_counts[c], off = g_offsets[c];
    float4 acc = make_float4(0.f, 0.f, 0.f, 0.f);
    for (int s0 = 0; s0 < cnt; s0 += 64) {
        int m = cnt - s0; if (m > 64) m = 64;
        if (t < m) idxs[t] = g_order[off + s0 + t];
        __syncthreads();
        for (int i = 0; i < m; i++) {
            const float4 v = *((const float4*)(feat + (size_t)idxs[i] * D_) + t);
            acc.x += v.x; acc.y += v.y; acc.z += v.z; acc.w += v.w;
        }
        __syncthreads();
    }
    float sc = (cnt > 0) ? 1.0f / (TEMP_ * (float)cnt) : 0.f;
    float4 r = make_float4(acc.x * sc, acc.y * sc, acc.z * sc, acc.w * sc);
    *((float4*)(g_Fagg + (size_t)c * D_) + t) = r;
}

// -------- 6) GEMM: sim[256,8192] = inputs @ F_agg^T (fp32, FFMA2) --------
// block tile: 128 (b) x 64 (c), K-chunk 32; 256 threads; thread tile 4b x 8c
#define GBT 128
#define GCT 64
#define GKB 32
__global__ void __launch_bounds__(256) k_gemm() {
    __shared__ __align__(16) float As[GBT][GKB + 1];  // pad -> conflict-free
    __shared__ __align__(16) float Bs[GKB][GCT + 2];  // even pad -> 8B-aligned f32x2
    int tid = threadIdx.x;
    int ctile = blockIdx.x & 127;          // 8192/64 = 128 c-tiles
    int btile = blockIdx.x >> 7;           // 2 b-tiles
    int b0 = btile * GBT, c0 = ctile * GCT;
    int bt = (tid >> 3) * 4;               // 32 b-groups of 4 rows
    int ct = (tid & 7) * 8;                // 8  c-groups of 8 cols
    unsigned long long acc[4][4];
#pragma unroll
    for (int i = 0; i < 4; i++)
#pragma unroll
        for (int j = 0; j < 4; j++) acc[i][j] = 0ULL;

    for (int k0 = 0; k0 < D_; k0 += GKB) {
#pragma unroll
        for (int i = 0; i < 16; i++) {                 // 128*32 / 256
            int idx = i * 256 + tid; int bb = idx >> 5, kk = idx & 31;
            As[bb][kk] = g_inputs[(size_t)(b0 + bb) * D_ + k0 + kk];
        }
#pragma unroll
        for (int i = 0; i < 8; i++) {                  // 64*32 / 256
            int idx = i * 256 + tid; int cc = idx >> 5, kk = idx & 31;
            Bs[kk][cc] = g_Fagg[(size_t)(c0 + cc) * D_ + k0 + kk];
        }
        __syncthreads();
#pragma unroll 8
        for (int kk = 0; kk < GKB; kk++) {
            unsigned long long aa[4], bv[4];
#pragma unroll
            for (int j = 0; j < 4; j++)
                bv[j] = *(const unsigned long long*)&Bs[kk][ct + 2 * j];
#pragma unroll
            for (int i = 0; i < 4; i++) {
                float av = As[bt + i][kk];
                aa[i] = pack2(av, av);
            }
#pragma unroll
            for (int i = 0; i < 4; i++)
#pragma unroll
                for (int j = 0; j < 4; j++) fma2(acc[i][j], aa[i], bv[j]);
        }
        __syncthreads();
    }
#pragma unroll
    for (int i = 0; i < 4; i++)
#pragma unroll
        for (int j = 0; j < 4; j++)
            *(unsigned long long*)&g_sim[(size_t)(b0 + bt + i) * C_ + c0 + ct + 2 * j] =
                acc[i][j];
}

// -------- 7) focal masked softmax per row: radix-select by cumulative mass --------
__global__ void __launch_bounds__(512) k_focal(const int* __restrict__ labels,
                                               const int* __restrict__ indexes) {
    __shared__ float se[C_];        // masked exps, target zeroed (32 KB)
    __shared__ float red[512];
    __shared__ float binM[256];
    __shared__ float sh_et;
    __shared__ unsigned sh_pref;
    __shared__ float sh_gAbove;
    const int T = 512;
    int b = blockIdx.x, t = threadIdx.x;
    int tgt = labels[indexes[b]];

    // exps with mask; stash e_target, zero it among negatives
    float ls = 0.f;
    for (int c = t; c < C_; c += T) {
        float e = 0.f;
        if (g_counts[c] > 0) e = expf(g_sim[(size_t)b * C_ + c]);
        if (c == tgt) { sh_et = e; e = 0.f; }
        se[c] = e; ls += e;
    }
    red[t] = ls; __syncthreads();
    for (int o = 256; o > 0; o >>= 1) { if (t < o) red[t] += red[t + o]; __syncthreads(); }
    float S = red[0];
    float target = TOPP_ * S;     // unnormalized crossing mass

    // 4-pass radix select (MSB->LSB on float bits; all e >= 0 so uint order == float order)
    unsigned pref = 0; float gAb = 0.f;   // gAb = mass of elements strictly above current value
    for (int l = 3; l >= 0; l--) {
        if (t < 256) binM[t] = 0.f;
        __syncthreads();
        int sh = l * 8;
        for (int c = t; c < C_; c += T) {
            float e = se[c];
            if (e > 0.f) {
                unsigned k = __float_as_uint(e);
                bool match = (((unsigned long long)k >> (sh + 8)) ==
                              ((unsigned long long)pref >> (sh + 8)));
                if (match) atomicAdd(&binM[(k >> sh) & 0xFFu], e);
            }
        }
        __syncthreads();
        if (t == 0) {
            float run = gAb; int sel = -1; float selRun = gAb;
            int lastnz = -1; float lastRun = gAb;
            for (int bi = 255; bi >= 0; bi--) {
                float bm = binM[bi];
                if (bm > 0.f && run + bm >= target) { sel = bi; selRun = run; break; }
                if (bm > 0.f) { lastnz = bi; lastRun = run; }
                run += bm;
            }
            if (sel < 0) { sel = lastnz; selRun = lastRun; }  // fp-rounding fallback
            sh_pref = pref | ((unsigned)sel << sh);
            sh_gAbove = selRun;
        }
        __syncthreads();
        pref = sh_pref; gAb = sh_gAbove;
        __syncthreads();
    }
    float v = __uint_as_float(pref);      // element value at mass crossing
    // position within tie-group of v: i0 = ceil((target - G>)/v); reference argmin picks
    // j-1 vs j by distance; j-1's value is the predecessor (min element > v).
    float i0f = ceilf((target - gAb) / v);
    float thr;
    if (i0f >= 2.0f || gAb <= 0.f) {
        thr = v;
    } else {
        unsigned pk = 0xFFFFFFFFu;
        for (int c = t; c < C_; c += T) {
            float e = se[c];
            if (e > v) { unsigned k = __float_as_uint(e); if (k < pk) pk = k; }
        }
        unsigned* redu = (unsigned*)red;
        redu[t] = pk; __syncthreads();
        for (int o = 256; o > 0; o >>= 1) {
            if (t < o) { unsigned a = redu[t], q = redu[t + o]; redu[t] = (a < q) ? a : q; }
            __syncthreads();
        }
        unsigned pm = redu[0];
        float pred = (pm == 0xFFFFFFFFu) ? v : __uint_as_float(pm);
        float d1 = target - gAb;          // |csum[j-1] - 0.1|*S
        float d2 = gAb + v - target;      // |csum[j]   - 0.1|*S
        thr = (d1 <= d2) ? pred : v;      // argmin picks first on tie -> j-1
        __syncthreads();
    }

    // kept negatives sum: elements >= thr survive
    float ks = 0.f;
    for (int c = t; c < C_; c += T) { float e = se[c]; if (e >= thr) ks += e; }
    red[t] = ks; __syncthreads();
    for (int o = 256; o > 0; o >>= 1) { if (t < o) red[t] += red[t + o]; __syncthreads(); }
    if (t == 0) {
        float et = sh_et;
        float denom = et + red[0] + EPS_;
        float p = et / denom;
        g_loss[b] = -logf(p + EPS_);
    }
}

// -------- 8) final mean --------
__global__ void k_final(float* out) {
    __shared__ float red[256];
    int t = threadIdx.x;
    red[t] = g_loss[t]; __syncthreads();
    for (int o = 128; o > 0; o >>= 1) { if (t < o) red[t] += red[t + o]; __syncthreads(); }
    if (t == 0) out[0] = red[0] * (1.0f / (float)B_);
}

extern "C" void kernel_launch(void* const* d_in, const int* in_sizes, int n_in,
                              void* d_out, int out_size) {
    (void)in_sizes; (void)n_in; (void)out_size;
    const float* results  = (const float*)d_in[0];
    const float* features = (const float*)d_in[1];
    const int*   indexes  = (const int*)d_in[2];
    const int*   labels   = (const int*)d_in[3];
    float* out = (float*)d_out;

    k_norm   <<<B_, 256>>>(results);
    k_zero   <<<C_ / 256, 256>>>();
    k_hist   <<<N_ / 256, 256>>>(labels);
    k_scan   <<<1, 1024>>>();
    k_scatter<<<N_ / 256, 256>>>(labels);
    k_agg    <<<C_, 256>>>(features);
    k_gemm   <<<256, 256>>>();
    k_focal  <<<B_, 512>>>(labels, indexes);
    k_final  <<<1, 256>>>(out);
}

// round 2
// speedup vs baseline: 1.0023x; 1.0023x over previous
#include <cuda_runtime.h>
#include <math.h>

#define B_    256
#define D_    1024
#define N_    65536
#define C_    8192
#define TEMP_ 0.05f
#define TOPP_ 0.1f
#define EPS_  1e-6f

// -------- scratch (device globals: no allocation allowed) --------
__device__ float g_inputs[B_ * D_];          // normalized inputs   (1 MB)
__device__ float g_Fagg[(size_t)C_ * D_];    // per-cluster mean / TEMP (32 MB)
__device__ int   g_counts[C_];
__device__ int   g_offsets[C_];
__device__ int   g_cursor[C_];
__device__ int   g_order[N_];
__device__ float g_sim[(size_t)B_ * C_];     // logits (8 MB)
__device__ float g_loss[B_];

// -------- packed f32x2 helpers (FFMA2) --------
__device__ __forceinline__ unsigned long long pack2(float x, float y) {
    unsigned long long r;
    asm("mov.b64 %0, {%1, %2};" : "=l"(r) : "f"(x), "f"(y));
    return r;
}
__device__ __forceinline__ void fma2(unsigned long long& d, unsigned long long a,
                                     unsigned long long b) {
    asm("fma.rn.f32x2 %0, %1, %2, %0;" : "+l"(d) : "l"(a), "l"(b));
}

// -------- 1) L2-normalize the query rows --------
__global__ void k_norm(const float* __restrict__ res) {
    __shared__ float red[256];
    int b = blockIdx.x, t = threadIdx.x;
    const float* row = res + (size_t)b * D_;
    float s = 0.f;
    for (int i = t; i < D_; i += 256) { float v = row[i]; s += v * v; }
    red[t] = s; __syncthreads();
    for (int o = 128; o > 0; o >>= 1) { if (t < o) red[t] += red[t + o]; __syncthreads(); }
    float inv = rsqrtf(red[0]);
    for (int i = t; i < D_; i += 256) g_inputs[(size_t)b * D_ + i] = row[i] * inv;
}

// -------- 2) histogram of labels --------
__global__ void k_zero() {
    int i = blockIdx.x * blockDim.x + threadIdx.x;
    if (i < C_) g_counts[i] = 0;
}
__global__ void k_hist(const int* __restrict__ labels) {
    int n = blockIdx.x * blockDim.x + threadIdx.x;
    if (n < N_) atomicAdd(&g_counts[labels[n]], 1);
}

// -------- 3) exclusive scan of counts (1 block, 1024 threads x 8) --------
__global__ void k_scan() {
    __shared__ int s[1024];
    int t = threadIdx.x;
    int base = t * 8;
    int v[8]; int tot = 0;
#pragma unroll
    for (int i = 0; i < 8; i++) { v[i] = g_counts[base + i]; tot += v[i]; }
    s[t] = tot; __syncthreads();
    for (int o = 1; o < 1024; o <<= 1) {
        int x = (t >= o) ? s[t - o] : 0;
        __syncthreads();
        s[t] += x;
        __syncthreads();
    }
    int excl = s[t] - tot;
#pragma unroll
    for (int i = 0; i < 8; i++) {
        g_offsets[base + i] = excl;
        g_cursor[base + i]  = excl;
        excl += v[i];
    }
}

// -------- 4) counting-sort scatter --------
__global__ void k_scatter(const int* __restrict__ labels) {
    int n = blockIdx.x * blockDim.x + threadIdx.x;
    if (n < N_) {
        int l = labels[n];
        int p = atomicAdd(&g_cursor[l], 1);
        g_order[p] = n;
    }
}

// -------- 5) per-cluster feature aggregation: F_agg[c] = sum/(TEMP*cnt) --------
__global__ void k_agg(const float* __restrict__ feat) {
    __shared__ int idxs[64];
    int c = blockIdx.x, t = threadIdx.x;
    int cnt = g_counts[c], off = g_offsets[c];
    float4 acc = make_float4(0.f, 0.f, 0.f, 0.f);
    for (int s0 = 0; s0 < cnt; s0 += 64) {
        int m = cnt - s0; if (m > 64) m = 64;
        if (t < m) idxs[t] = g_order[off + s0 + t];
        __syncthreads();
        for (int i = 0; i < m; i++) {
            const float4 v = *((const float4*)(feat + (size_t)idxs[i] * D_) + t);
            acc.x += v.x; acc.y += v.y; acc.z += v.z; acc.w += v.w;
        }
        __syncthreads();
    }
    float sc = (cnt > 0) ? 1.0f / (TEMP_ * (float)cnt) : 0.f;
    float4 r = make_float4(acc.x * sc, acc.y * sc, acc.z * sc, acc.w * sc);
    *((float4*)(g_Fagg + (size_t)c * D_) + t) = r;
}

// -------- 6) GEMM: sim[256,8192] = inputs @ F_agg^T (fp32, FFMA2) --------
// block tile: 128 (b) x 64 (c), K-chunk 32; 256 threads; thread tile 4b x 8c
#define GBT 128
#define GCT 64
#define GKB 32
__global__ void __launch_bounds__(256) k_gemm() {
    __shared__ __align__(16) float As[GBT][GKB + 1];  // pad -> conflict-free
    __shared__ __align__(16) float Bs[GKB][GCT + 2];  // even pad -> 8B-aligned f32x2
    int tid = threadIdx.x;
    int ctile = blockIdx.x & 127;          // 8192/64 = 128 c-tiles
    int btile = blockIdx.x >> 7;           // 2 b-tiles
    int b0 = btile * GBT, c0 = ctile * GCT;
    int bt = (tid >> 3) * 4;               // 32 b-groups of 4 rows
    int ct = (tid & 7) * 8;                // 8  c-groups of 8 cols
    unsigned long long acc[4][4];
#pragma unroll
    for (int i = 0; i < 4; i++)
#pragma unroll
        for (int j = 0; j < 4; j++) acc[i][j] = 0ULL;

    for (int k0 = 0; k0 < D_; k0 += GKB) {
#pragma unroll
        for (int i = 0; i < 16; i++) {                 // 128*32 / 256
            int idx = i * 256 + tid; int bb = idx >> 5, kk = idx & 31;
            As[bb][kk] = g_inputs[(size_t)(b0 + bb) * D_ + k0 + kk];
        }
#pragma unroll
        for (int i = 0; i < 8; i++) {                  // 64*32 / 256
            int idx = i * 256 + tid; int cc = idx >> 5, kk = idx & 31;
            Bs[kk][cc] = g_Fagg[(size_t)(c0 + cc) * D_ + k0 + kk];
        }
        __syncthreads();
#pragma unroll 8
        for (int kk = 0; kk < GKB; kk++) {
            unsigned long long aa[4], bv[4];
#pragma unroll
            for (int j = 0; j < 4; j++)
                bv[j] = *(const unsigned long long*)&Bs[kk][ct + 2 * j];
#pragma unroll
            for (int i = 0; i < 4; i++) {
                float av = As[bt + i][kk];
                aa[i] = pack2(av, av);
            }
#pragma unroll
            for (int i = 0; i < 4; i++)
#pragma unroll
                for (int j = 0; j < 4; j++) fma2(acc[i][j], aa[i], bv[j]);
        }
        __syncthreads();
    }
#pragma unroll
    for (int i = 0; i < 4; i++)
#pragma unroll
        for (int j = 0; j < 4; j++)
            *(unsigned long long*)&g_sim[(size_t)(b0 + bt + i) * C_ + c0 + ct + 2 * j] =
                acc[i][j];
}

// -------- 7) focal masked softmax per row: radix-select by cumulative mass --------
__global__ void __launch_bounds__(512) k_focal(const int* __restrict__ labels,
                                               const int* __restrict__ indexes) {
    __shared__ float se[C_];        // masked exps, target zeroed (32 KB)
    __shared__ float red[512];
    __shared__ float binM[256];
    __shared__ float sh_et;
    __shared__ unsigned sh_pref;
    __shared__ float sh_gAbove;
    const int T = 512;
    int b = blockIdx.x, t = threadIdx.x;
    int tgt = labels[indexes[b]];

    // exps with mask; stash e_target, zero it among negatives
    float ls = 0.f;
    for (int c = t; c < C_; c += T) {
        float e = 0.f;
        if (g_counts[c] > 0) e = expf(g_sim[(size_t)b * C_ + c]);
        if (c == tgt) { sh_et = e; e = 0.f; }
        se[c] = e; ls += e;
    }
    red[t] = ls; __syncthreads();
    for (int o = 256; o > 0; o >>= 1) { if (t < o) red[t] += red[t + o]; __syncthreads(); }
    float S = red[0];
    float target = TOPP_ * S;     // unnormalized crossing mass

    // 4-pass radix select (MSB->LSB on float bits; all e >= 0 so uint order == float order)
    unsigned pref = 0; float gAb = 0.f;   // gAb = mass of elements strictly above current value
    for (int l = 3; l >= 0; l--) {
        if (t < 256) binM[t] = 0.f;
        __syncthreads();
        int sh = l * 8;
        for (int c = t; c < C_; c += T) {
            float e = se[c];
            if (e > 0.f) {
                unsigned k = __float_as_uint(e);
                bool match = (((unsigned long long)k >> (sh + 8)) ==
                              ((unsigned long long)pref >> (sh + 8)));
                if (match) atomicAdd(&binM[(k >> sh) & 0xFFu], e);
            }
        }
        __syncthreads();
        if (t == 0) {
            float run = gAb; int sel = -1; float selRun = gAb;
            int lastnz = -1; float lastRun = gAb;
            for (int bi = 255; bi >= 0; bi--) {
                float bm = binM[bi];
                if (bm > 0.f && run + bm >= target) { sel = bi; selRun = run; break; }
                if (bm > 0.f) { lastnz = bi; lastRun = run; }
                run += bm;
            }
            if (sel < 0) { sel = lastnz; selRun = lastRun; }  // fp-rounding fallback
            sh_pref = pref | ((unsigned)sel << sh);
            sh_gAbove = selRun;
        }
        __syncthreads();
        pref = sh_pref; gAb = sh_gAbove;
        __syncthreads();
    }
    float v = __uint_as_float(pref);      // element value at mass crossing
    // position within tie-group of v: i0 = ceil((target - G>)/v); reference argmin picks
    // j-1 vs j by distance; j-1's value is the predecessor (min element > v).
    float i0f = ceilf((target - gAb) / v);
    float thr;
    if (i0f >= 2.0f || gAb <= 0.f) {
        thr = v;
    } else {
        unsigned pk = 0xFFFFFFFFu;
        for (int c = t; c < C_; c += T) {
            float e = se[c];
            if (e > v) { unsigned k = __float_as_uint(e); if (k < pk) pk = k; }
        }
        unsigned* redu = (unsigned*)red;
        redu[t] = pk; __syncthreads();
        for (int o = 256; o > 0; o >>= 1) {
            if (t < o) { unsigned a = redu[t], q = redu[t + o]; redu[t] = (a < q) ? a : q; }
            __syncthreads();
        }
        unsigned pm = redu[0];
        float pred = (pm == 0xFFFFFFFFu) ? v : __uint_as_float(pm);
        float d1 = target - gAb;          // |csum[j-1] - 0.1|*S
        float d2 = gAb + v - target;      // |csum[j]   - 0.1|*S
        thr = (d1 <= d2) ? pred : v;      // argmin picks first on tie -> j-1
        __syncthreads();
    }

    // kept negatives sum: elements >= thr survive
    float ks = 0.f;
    for (int c = t; c < C_; c += T) { float e = se[c]; if (e >= thr) ks += e; }
    red[t] = ks; __syncthreads();
    for (int o = 256; o > 0; o >>= 1) { if (t < o) red[t] += red[t + o]; __syncthreads(); }
    if (t == 0) {
        float et = sh_et;
        float denom = et + red[0] + EPS_;
        float p = et / denom;
        g_loss[b] = -logf(p + EPS_);
    }
}

// -------- 8) final mean --------
__global__ void k_final(float* out) {
    __shared__ float red[256];
    int t = threadIdx.x;
    red[t] = g_loss[t]; __syncthreads();
    for (int o = 128; o > 0; o >>= 1) { if (t < o) red[t] += red[t + o]; __syncthreads(); }
    if (t == 0) out[0] = red[0] * (1.0f / (float)B_);
}

extern "C" void kernel_launch(void* const* d_in, const int* in_sizes, int n_in,
                              void* d_out, int out_size) {
    (void)in_sizes; (void)n_in; (void)out_size;
    const float* results  = (const float*)d_in[0];
    const float* features = (const float*)d_in[1];
    const int*   indexes  = (const int*)d_in[2];
    const int*   labels   = (const int*)d_in[3];
    float* out = (float*)d_out;

    k_norm   <<<B_, 256>>>(results);
    k_zero   <<<C_ / 256, 256>>>();
    k_hist   <<<N_ / 256, 256>>>(labels);
    k_scan   <<<1, 1024>>>();
    k_scatter<<<N_ / 256, 256>>>(labels);
    k_agg    <<<C_, 256>>>(features);
    k_gemm   <<<256, 256>>>();
    k_focal  <<<B_, 512>>>(labels, indexes);
    k_final  <<<1, 256>>>(out);
}

// round 3
// speedup vs baseline: 1.0032x; 1.0009x over previous
#include <cuda_runtime.h>
#include <math.h>

#define B_    256
#define D_    1024
#define N_    65536
#define C_    8192
#define TEMP_ 0.05f
#define TOPP_ 0.1f
#define EPS_  1e-6f

// -------- scratch (device globals: no allocation allowed) --------
__device__ float g_inputs[B_ * D_];          // normalized inputs   (1 MB)
__device__ float g_Fagg[(size_t)C_ * D_];    // per-cluster mean / TEMP (32 MB)
__device__ int   g_counts[C_];
__device__ int   g_offsets[C_];
__device__ int   g_cursor[C_];
__device__ int   g_order[N_];
__device__ float g_sim[(size_t)B_ * C_];     // logits (8 MB)
__device__ float g_loss[B_];

// -------- packed f32x2 helpers (FFMA2) --------
__device__ __forceinline__ unsigned long long pack2(float x, float y) {
    unsigned long long r;
    asm("mov.b64 %0, {%1, %2};" : "=l"(r) : "f"(x), "f"(y));
    return r;
}
__device__ __forceinline__ void fma2(unsigned long long& d, unsigned long long a,
                                     unsigned long long b) {
    asm("fma.rn.f32x2 %0, %1, %2, %0;" : "+l"(d) : "l"(a), "l"(b));
}

// -------- 1) L2-normalize the query rows --------
__global__ void k_norm(const float* __restrict__ res) {
    __shared__ float red[256];
    int b = blockIdx.x, t = threadIdx.x;
    const float* row = res + (size_t)b * D_;
    float s = 0.f;
    for (int i = t; i < D_; i += 256) { float v = row[i]; s += v * v; }
    red[t] = s; __syncthreads();
    for (int o = 128; o > 0; o >>= 1) { if (t < o) red[t] += red[t + o]; __syncthreads(); }
    float inv = rsqrtf(red[0]);
    for (int i = t; i < D_; i += 256) g_inputs[(size_t)b * D_ + i] = row[i] * inv;
}

// -------- 2) histogram of labels --------
__global__ void k_zero() {
    int i = blockIdx.x * blockDim.x + threadIdx.x;
    if (i < C_) g_counts[i] = 0;
}
__global__ void k_hist(const int* __restrict__ labels) {
    int n = blockIdx.x * blockDim.x + threadIdx.x;
    if (n < N_) atomicAdd(&g_counts[labels[n]], 1);
}

// -------- 3) exclusive scan of counts (1 block, 1024 threads x 8) --------
__global__ void k_scan() {
    __shared__ int s[1024];
    int t = threadIdx.x;
    int base = t * 8;
    int v[8]; int tot = 0;
#pragma unroll
    for (int i = 0; i < 8; i++) { v[i] = g_counts[base + i]; tot += v[i]; }
    s[t] = tot; __syncthreads();
    for (int o = 1; o < 1024; o <<= 1) {
        int x = (t >= o) ? s[t - o] : 0;
        __syncthreads();
        s[t] += x;
        __syncthreads();
    }
    int excl = s[t] - tot;
#pragma unroll
    for (int i = 0; i < 8; i++) {
        g_offsets[base + i] = excl;
        g_cursor[base + i]  = excl;
        excl += v[i];
    }
}

// -------- 4) counting-sort scatter --------
__global__ void k_scatter(const int* __restrict__ labels) {
    int n = blockIdx.x * blockDim.x + threadIdx.x;
    if (n < N_) {
        int l = labels[n];
        int p = atomicAdd(&g_cursor[l], 1);
        g_order[p] = n;
    }
}

// -------- 5) per-cluster feature aggregation: F_agg[c] = sum/(TEMP*cnt) --------
__global__ void k_agg(const float* __restrict__ feat) {
    __shared__ int idxs[64];
    int c = blockIdx.x, t = threadIdx.x;
    int cnt = g_counts[c], off = g_offsets[c];
    float4 acc = make_float4(0.f, 0.f, 0.f, 0.f);
    for (int s0 = 0; s0 < cnt; s0 += 64) {
        int m = cnt - s0; if (m > 64) m = 64;
        if (t < m) idxs[t] = g_order[off + s0 + t];
        __syncthreads();
        for (int i = 0; i < m; i++) {
            const float4 v = *((const float4*)(feat + (size_t)idxs[i] * D_) + t);
            acc.x += v.x; acc.y += v.y; acc.z += v.z; acc.w += v.w;
        }
        __syncthreads();
    }
    float sc = (cnt > 0) ? 1.0f / (TEMP_ * (float)cnt) : 0.f;
    float4 r = make_float4(acc.x * sc, acc.y * sc, acc.z * sc, acc.w * sc);
    *((float4*)(g_Fagg + (size_t)c * D_) + t) = r;
}

// -------- 6) GEMM: sim[256,8192] = inputs @ F_agg^T (fp32, FFMA2) --------
// block tile: 128 (b) x 64 (c), K-chunk 32; 256 threads; thread tile 4b x 8c
#define GBT 128
#define GCT 64
#define GKB 32
__global__ void __launch_bounds__(256) k_gemm() {
    __shared__ __align__(16) float As[GBT][GKB + 1];  // pad -> conflict-free
    __shared__ __align__(16) float Bs[GKB][GCT + 2];  // even pad -> 8B-aligned f32x2
    int tid = threadIdx.x;
    int ctile = blockIdx.x & 127;          // 8192/64 = 128 c-tiles
    int btile = blockIdx.x >> 7;           // 2 b-tiles
    int b0 = btile * GBT, c0 = ctile * GCT;
    int bt = (tid >> 3) * 4;               // 32 b-groups of 4 rows
    int ct = (tid & 7) * 8;                // 8  c-groups of 8 cols
    unsigned long long acc[4][4];
#pragma unroll
    for (int i = 0; i < 4; i++)
#pragma unroll
        for (int j = 0; j < 4; j++) acc[i][j] = 0ULL;

    for (int k0 = 0; k0 < D_; k0 += GKB) {
#pragma unroll
        for (int i = 0; i < 16; i++) {                 // 128*32 / 256
            int idx = i * 256 + tid; int bb = idx >> 5, kk = idx & 31;
            As[bb][kk] = g_inputs[(size_t)(b0 + bb) * D_ + k0 + kk];
        }
#pragma unroll
        for (int i = 0; i < 8; i++) {                  // 64*32 / 256
            int idx = i * 256 + tid; int cc = idx >> 5, kk = idx & 31;
            Bs[kk][cc] = g_Fagg[(size_t)(c0 + cc) * D_ + k0 + kk];
        }
        __syncthreads();
#pragma unroll 8
        for (int kk = 0; kk < GKB; kk++) {
            unsigned long long aa[4], bv[4];
#pragma unroll
            for (int j = 0; j < 4; j++)
                bv[j] = *(const unsigned long long*)&Bs[kk][ct + 2 * j];
#pragma unroll
            for (int i = 0; i < 4; i++) {
                float av = As[bt + i][kk];
                aa[i] = pack2(av, av);
            }
#pragma unroll
            for (int i = 0; i < 4; i++)
#pragma unroll
                for (int j = 0; j < 4; j++) fma2(acc[i][j], aa[i], bv[j]);
        }
        __syncthreads();
    }
#pragma unroll
    for (int i = 0; i < 4; i++)
#pragma unroll
        for (int j = 0; j < 4; j++)
            *(unsigned long long*)&g_sim[(size_t)(b0 + bt + i) * C_ + c0 + ct + 2 * j] =
                acc[i][j];
}

// -------- 7) focal masked softmax per row: radix-select by cumulative mass --------
__global__ void __launch_bounds__(512) k_focal(const int* __restrict__ labels,
                                               const int* __restrict__ indexes) {
    __shared__ float se[C_];        // masked exps, target zeroed (32 KB)
    __shared__ float red[512];
    __shared__ float binM[256];
    __shared__ float sh_et;
    __shared__ unsigned sh_pref;
    __shared__ float sh_gAbove;
    const int T = 512;
    int b = blockIdx.x, t = threadIdx.x;
    int tgt = labels[indexes[b]];

    // exps with mask; stash e_target, zero it among negatives
    float ls = 0.f;
    for (int c = t; c < C_; c += T) {
        float e = 0.f;
        if (g_counts[c] > 0) e = expf(g_sim[(size_t)b * C_ + c]);
        if (c == tgt) { sh_et = e; e = 0.f; }
        se[c] = e; ls += e;
    }
    red[t] = ls; __syncthreads();
    for (int o = 256; o > 0; o >>= 1) { if (t < o) red[t] += red[t + o]; __syncthreads(); }
    float S = red[0];
    float target = TOPP_ * S;     // unnormalized crossing mass

    // 4-pass radix select (MSB->LSB on float bits; all e >= 0 so uint order == float order)
    unsigned pref = 0; float gAb = 0.f;   // gAb = mass of elements strictly above current value
    for (int l = 3; l >= 0; l--) {
        if (t < 256) binM[t] = 0.f;
        __syncthreads();
        int sh = l * 8;
        for (int c = t; c < C_; c += T) {
            float e = se[c];
            if (e > 0.f) {
                unsigned k = __float_as_uint(e);
                bool match = (((unsigned long long)k >> (sh + 8)) ==
                              ((unsigned long long)pref >> (sh + 8)));
                if (match) atomicAdd(&binM[(k >> sh) & 0xFFu], e);
            }
        }
        __syncthreads();
        if (t == 0) {
            float run = gAb; int sel = -1; float selRun = gAb;
            int lastnz = -1; float lastRun = gAb;
            for (int bi = 255; bi >= 0; bi--) {
                float bm = binM[bi];
                if (bm > 0.f && run + bm >= target) { sel = bi; selRun = run; break; }
                if (bm > 0.f) { lastnz = bi; lastRun = run; }
                run += bm;
            }
            if (sel < 0) { sel = lastnz; selRun = lastRun; }  // fp-rounding fallback
            sh_pref = pref | ((unsigned)sel << sh);
            sh_gAbove = selRun;
        }
        __syncthreads();
        pref = sh_pref; gAb = sh_gAbove;
        __syncthreads();
    }
    float v = __uint_as_float(pref);      // element value at mass crossing
    // position within tie-group of v: i0 = ceil((target - G>)/v); reference argmin picks
    // j-1 vs j by distance; j-1's value is the predecessor (min element > v).
    float i0f = ceilf((target - gAb) / v);
    float thr;
    if (i0f >= 2.0f || gAb <= 0.f) {
        thr = v;
    } else {
        unsigned pk = 0xFFFFFFFFu;
        for (int c = t; c < C_; c += T) {
            float e = se[c];
            if (e > v) { unsigned k = __float_as_uint(e); if (k < pk) pk = k; }
        }
        unsigned* redu = (unsigned*)red;
        redu[t] = pk; __syncthreads();
        for (int o = 256; o > 0; o >>= 1) {
            if (t < o) { unsigned a = redu[t], q = redu[t + o]; redu[t] = (a < q) ? a : q; }
            __syncthreads();
        }
        unsigned pm = redu[0];
        float pred = (pm == 0xFFFFFFFFu) ? v : __uint_as_float(pm);
        float d1 = target - gAb;          // |csum[j-1] - 0.1|*S
        float d2 = gAb + v - target;      // |csum[j]   - 0.1|*S
        thr = (d1 <= d2) ? pred : v;      // argmin picks first on tie -> j-1
        __syncthreads();
    }

    // kept negatives sum: elements >= thr survive
    float ks = 0.f;
    for (int c = t; c < C_; c += T) { float e = se[c]; if (e >= thr) ks += e; }
    red[t] = ks; __syncthreads();
    for (int o = 256; o > 0; o >>= 1) { if (t < o) red[t] += red[t + o]; __syncthreads(); }
    if (t == 0) {
        float et = sh_et;
        float denom = et + red[0] + EPS_;
        float p = et / denom;
        g_loss[b] = -logf(p + EPS_);
    }
}

// -------- 8) final mean --------
__global__ void k_final(float* out) {
    __shared__ float red[256];
    int t = threadIdx.x;
    red[t] = g_loss[t]; __syncthreads();
    for (int o = 128; o > 0; o >>= 1) { if (t < o) red[t] += red[t + o]; __syncthreads(); }
    if (t == 0) out[0] = red[0] * (1.0f / (float)B_);
}

extern "C" void kernel_launch(void* const* d_in, const int* in_sizes, int n_in,
                              void* d_out, int out_size) {
    (void)in_sizes; (void)n_in; (void)out_size;
    const float* results  = (const float*)d_in[0];
    const float* features = (const float*)d_in[1];
    const int*   indexes  = (const int*)d_in[2];
    const int*   labels   = (const int*)d_in[3];
    float* out = (float*)d_out;

    k_norm   <<<B_, 256>>>(results);
    k_zero   <<<C_ / 256, 256>>>();
    k_hist   <<<N_ / 256, 256>>>(labels);
    k_scan   <<<1, 1024>>>();
    k_scatter<<<N_ / 256, 256>>>(labels);
    k_agg    <<<C_, 256>>>(features);
    k_gemm   <<<256, 256>>>();
    k_focal  <<<B_, 512>>>(labels, indexes);
    k_final  <<<1, 256>>>(out);
}

// round 5
// speedup vs baseline: 1.4232x; 1.4187x over previous
#include <cuda_runtime.h>
#include <cuda_bf16.h>
#include <math.h>
#include <stdint.h>

#define B_    256
#define D_    1024
#define N_    65536
#define C_    8192
#define TEMP_ 0.05f
#define TOPP_ 0.1f
#define EPS_  1e-6f

// -------- scratch (device globals: no allocation allowed) --------
__device__ __nv_bfloat16 g_A2[(size_t)B_ * 2048];   // [b][k]: 0..1023 hi, 1024..2047 lo (1 MB)
__device__ __nv_bfloat16 g_B2[(size_t)C_ * 2048];   // [c][k]: hi | lo (32 MB)
__device__ int   g_counts[C_];
__device__ int   g_offsets[C_];
__device__ int   g_cursor[C_];
__device__ int   g_order[N_];
__device__ float g_sim[(size_t)B_ * C_];            // logits (8 MB)
__device__ float g_loss[B_];

__device__ __forceinline__ uint32_t smem_u32(const void* p) {
    uint32_t a;
    asm("{ .reg .u64 t; cvta.to.shared.u64 t, %1; cvt.u32.u64 %0, t; }" : "=r"(a) : "l"(p));
    return a;
}
__device__ __forceinline__ uint32_t swz128(uint32_t o) { return o ^ ((o >> 3) & 0x70u); }

// -------- 1) L2-normalize queries, emit bf16 hi/lo split --------
__global__ void k_norm(const float* __restrict__ res) {
    __shared__ float red[256];
    int b = blockIdx.x, t = threadIdx.x;
    const float* row = res + (size_t)b * D_;
    float s = 0.f;
    for (int i = t; i < D_; i += 256) { float v = row[i]; s += v * v; }
    red[t] = s; __syncthreads();
    for (int o = 128; o > 0; o >>= 1) { if (t < o) red[t] += red[t + o]; __syncthreads(); }
    float inv = rsqrtf(red[0]);
    for (int i = t; i < D_; i += 256) {
        float v = row[i] * inv;
        __nv_bfloat16 hi = __float2bfloat16_rn(v);
        __nv_bfloat16 lo = __float2bfloat16_rn(v - __bfloat162float(hi));
        g_A2[(size_t)b * 2048 + i]        = hi;
        g_A2[(size_t)b * 2048 + 1024 + i] = lo;
    }
}

// -------- 2) histogram of labels --------
__global__ void k_zero() {
    int i = blockIdx.x * blockDim.x + threadIdx.x;
    if (i < C_) g_counts[i] = 0;
}
__global__ void k_hist(const int* __restrict__ labels) {
    int n = blockIdx.x * blockDim.x + threadIdx.x;
    if (n < N_) atomicAdd(&g_counts[labels[n]], 1);
}

// -------- 3) exclusive scan of counts: 256 thr x 32 seq + warp scan --------
__global__ void k_scan() {
    __shared__ int wtot[8];
    int t = threadIdx.x, lane = t & 31, w = t >> 5;
    int base = t * 32;
    int v[32]; int tot = 0;
#pragma unroll
    for (int i = 0; i < 32; i++) { v[i] = g_counts[base + i]; tot += v[i]; }
    int inc = tot;
#pragma unroll
    for (int o = 1; o < 32; o <<= 1) {
        int x = __shfl_up_sync(0xFFFFFFFFu, inc, o);
        if (lane >= o) inc += x;
    }
    if (lane == 31) wtot[w] = inc;
    __syncthreads();
    if (t == 0) {
        int run = 0;
#pragma unroll
        for (int j = 0; j < 8; j++) { int x = wtot[j]; wtot[j] = run; run += x; }
    }
    __syncthreads();
    int excl = wtot[w] + inc - tot;
#pragma unroll
    for (int i = 0; i < 32; i++) {
        g_offsets[base + i] = excl;
        g_cursor[base + i]  = excl;
        excl += v[i];
    }
}

// -------- 4) counting-sort scatter --------
__global__ void k_scatter(const int* __restrict__ labels) {
    int n = blockIdx.x * blockDim.x + threadIdx.x;
    if (n < N_) {
        int l = labels[n];
        int p = atomicAdd(&g_cursor[l], 1);
        g_order[p] = n;
    }
}

// -------- 5) per-cluster mean/TEMP, emit bf16 hi/lo split --------
__global__ void k_agg(const float* __restrict__ feat) {
    __shared__ int idxs[64];
    int c = blockIdx.x, t = threadIdx.x;
    int cnt = g_counts[c], off = g_offsets[c];
    float4 acc = make_float4(0.f, 0.f, 0.f, 0.f);
    for (int s0 = 0; s0 < cnt; s0 += 64) {
        int m = cnt - s0; if (m > 64) m = 64;
        if (t < m) idxs[t] = g_order[off + s0 + t];
        __syncthreads();
        for (int i = 0; i < m; i++) {
            const float4 v = *((const float4*)(feat + (size_t)idxs[i] * D_) + t);
            acc.x += v.x; acc.y += v.y; acc.z += v.z; acc.w += v.w;
        }
        __syncthreads();
    }
    float sc = (cnt > 0) ? 1.0f / (TEMP_ * (float)cnt) : 0.f;
    float r0 = acc.x * sc, r1 = acc.y * sc, r2 = acc.z * sc, r3 = acc.w * sc;
    __nv_bfloat16 h0 = __float2bfloat16_rn(r0), h1 = __float2bfloat16_rn(r1);
    __nv_bfloat16 h2 = __float2bfloat16_rn(r2), h3 = __float2bfloat16_rn(r3);
    __nv_bfloat16 l0 = __float2bfloat16_rn(r0 - __bfloat162float(h0));
    __nv_bfloat16 l1 = __float2bfloat16_rn(r1 - __bfloat162float(h1));
    __nv_bfloat16 l2 = __float2bfloat16_rn(r2 - __bfloat162float(h2));
    __nv_bfloat16 l3 = __float2bfloat16_rn(r3 - __bfloat162float(h3));
    __nv_bfloat16* rowp = g_B2 + (size_t)c * 2048;
    __nv_bfloat162 hA; hA.x = h0; hA.y = h1;
    __nv_bfloat162 hB; hB.x = h2; hB.y = h3;
    __nv_bfloat162 lA; lA.x = l0; lA.y = l1;
    __nv_bfloat162 lB; lB.x = l2; lB.y = l3;
    *(__nv_bfloat162*)(rowp + 4 * t)            = hA;
    *(__nv_bfloat162*)(rowp + 4 * t + 2)        = hB;
    *(__nv_bfloat162*)(rowp + 1024 + 4 * t)     = lA;
    *(__nv_bfloat162*)(rowp + 1024 + 4 * t + 2) = lB;
}

// -------- 6) GEMM: sim[256,8192] = A2 @ B2^T via mma.sync (HMMA bf16) --------
// Block 128(m) x 128(n); 8 warps as 4x2 -> warp tile 32m x 64n.
// 48 virtual K-chunks of 64 bf16 (hi*hi, lo*hi, hi*lo). Single 32KB smem buffer,
// register prefetch of next chunk overlaps LDG with MMA.
__global__ void __launch_bounds__(256, 1) k_gemm_mma() {
    __shared__ __align__(1024) __nv_bfloat16 shA[128 * 64];  // 16 KB, swizzled 128B rows
    __shared__ __align__(1024) __nv_bfloat16 shB[128 * 64];  // 16 KB
    uint32_t sA = smem_u32(shA), sB = smem_u32(shB);
    int tid = threadIdx.x, wid = tid >> 5, l = tid & 31;
    int nt = blockIdx.x & 63, mt = blockIdx.x >> 6;
    int b0 = mt * 128, c0 = nt * 128;
    int mw = wid >> 1, nw = wid & 1;            // warp grid 4x2

    float acc[2][8][4];
#pragma unroll
    for (int mi = 0; mi < 2; mi++)
#pragma unroll
        for (int ni = 0; ni < 8; ni++)
#pragma unroll
            for (int r = 0; r < 4; r++) acc[mi][ni][r] = 0.f;

    int ur = tid >> 3, usg = tid & 7;           // this thread's uint4 slot: rows ur, ur+32, ...
    uint32_t so[4];
#pragma unroll
    for (int i = 0; i < 4; i++) so[i] = swz128((uint32_t)((ur + i * 32) * 128 + usg * 16));

    uint4 pa[4], pb[4];
    // preload chunk 0 (vc=0: ka=0, kb=0)
    {
        const uint4* gA = (const uint4*)(g_A2 + (size_t)b0 * 2048);
        const uint4* gB = (const uint4*)(g_B2 + (size_t)c0 * 2048);
#pragma unroll
        for (int i = 0; i < 4; i++) {
            pa[i] = gA[(size_t)(ur + i * 32) * 256 + usg];
            pb[i] = gB[(size_t)(ur + i * 32) * 256 + usg];
        }
    }

    for (int vc = 0; vc < 48; vc++) {
        // store prefetched chunk vc into smem
#pragma unroll
        for (int i = 0; i < 4; i++) {
            asm volatile("st.shared.v4.b32 [%0], {%1, %2, %3, %4};"
                         :: "r"(sA + so[i]), "r"(pa[i].x), "r"(pa[i].y), "r"(pa[i].z), "r"(pa[i].w) : "memory");
            asm volatile("st.shared.v4.b32 [%0], {%1, %2, %3, %4};"
                         :: "r"(sB + so[i]), "r"(pb[i].x), "r"(pb[i].y), "r"(pb[i].z), "r"(pb[i].w) : "memory");
        }
        __syncthreads();

        // issue global loads for chunk vc+1 (latency hidden behind MMA)
        if (vc < 47) {
            int v2 = vc + 1;
            int ka = (v2 < 32) ? v2 : v2 - 32;   // A: hi 0..15 | lo 16..31
            int kb = (v2 < 16) ? v2 : v2 - 16;   // B: hi 0..15 | lo 16..31
            const uint4* gA = (const uint4*)(g_A2 + (size_t)b0 * 2048 + ka * 64);
            const uint4* gB = (const uint4*)(g_B2 + (size_t)c0 * 2048 + kb * 64);
#pragma unroll
            for (int i = 0; i < 4; i++) {
                pa[i] = gA[(size_t)(ur + i * 32) * 256 + usg];
                pb[i] = gB[(size_t)(ur + i * 32) * 256 + usg];
            }
        }

        // compute: 4 k16 steps over the 64-wide chunk
#pragma unroll
        for (int kk = 0; kk < 4; kk++) {
            uint32_t a[2][4];
#pragma unroll
            for (int mi = 0; mi < 2; mi++) {
                uint32_t row = mw * 32 + mi * 16 + (l & 15);
                uint32_t addr = sA + swz128(row * 128 + kk * 32 + ((l >> 4) & 1) * 16);
                asm volatile("ldmatrix.sync.aligned.m8n8.x4.shared.b16 {%0,%1,%2,%3}, [%4];"
                             : "=r"(a[mi][0]), "=r"(a[mi][1]), "=r"(a[mi][2]), "=r"(a[mi][3])
                             : "r"(addr));
            }
            uint32_t bfr[8][2];
#pragma unroll
            for (int ni = 0; ni < 8; ni++) {
                uint32_t row = nw * 64 + ni * 8 + (l & 7);
                uint32_t addr = sB + swz128(row * 128 + kk * 32 + ((l >> 3) & 1) * 16);
                asm volatile("ldmatrix.sync.aligned.m8n8.x2.shared.b16 {%0,%1}, [%2];"
                             : "=r"(bfr[ni][0]), "=r"(bfr[ni][1]) : "r"(addr));
            }
#pragma unroll
            for (int mi = 0; mi < 2; mi++)
#pragma unroll
                for (int ni = 0; ni < 8; ni++)
                    asm volatile(
                        "mma.sync.aligned.m16n8k16.row.col.f32.bf16.bf16.f32 "
                        "{%0,%1,%2,%3}, {%4,%5,%6,%7}, {%8,%9}, {%0,%1,%2,%3};"
                        : "+f"(acc[mi][ni][0]), "+f"(acc[mi][ni][1]),
                          "+f"(acc[mi][ni][2]), "+f"(acc[mi][ni][3])
                        : "r"(a[mi][0]), "r"(a[mi][1]), "r"(a[mi][2]), "r"(a[mi][3]),
                          "r"(bfr[ni][0]), "r"(bfr[ni][1]));
        }
        __syncthreads();
    }

    // epilogue: thread (gr, gc) of each m16n8 fragment
    int gr = l >> 2, gc = (l & 3) * 2;
#pragma unroll
    for (int mi = 0; mi < 2; mi++) {
        int row = b0 + mw * 32 + mi * 16 + gr;
#pragma unroll
        for (int ni = 0; ni < 8; ni++) {
            int col = c0 + nw * 64 + ni * 8 + gc;
            float2 v0; v0.x = acc[mi][ni][0]; v0.y = acc[mi][ni][1];
            float2 v1; v1.x = acc[mi][ni][2]; v1.y = acc[mi][ni][3];
            *(float2*)&g_sim[(size_t)row * C_ + col]       = v0;
            *(float2*)&g_sim[(size_t)(row + 8) * C_ + col] = v1;
        }
    }
}

// -------- 7) focal masked softmax per row: radix-select by cumulative mass --------
__global__ void __launch_bounds__(512) k_focal(const int* __restrict__ labels,
                                               const int* __restrict__ indexes) {
    __shared__ float se[C_];        // masked exps, target zeroed (32 KB)
    __shared__ float red[512];
    __shared__ float binM[256];
    __shared__ float sh_et;
    __shared__ unsigned sh_pref;
    __shared__ float sh_gAbove;
    const int T = 512;
    int b = blockIdx.x, t = threadIdx.x;
    int tgt = labels[indexes[b]];

    float ls = 0.f;
    for (int c = t; c < C_; c += T) {
        float e = 0.f;
        if (g_counts[c] > 0) e = expf(g_sim[(size_t)b * C_ + c]);
        if (c == tgt) { sh_et = e; e = 0.f; }
        se[c] = e; ls += e;
    }
    red[t] = ls; __syncthreads();
    for (int o = 256; o > 0; o >>= 1) { if (t < o) red[t] += red[t + o]; __syncthreads(); }
    float S = red[0];
    float target = TOPP_ * S;

    unsigned pref = 0; float gAb = 0.f;
    for (int lvl = 3; lvl >= 0; lvl--) {
        if (t < 256) binM[t] = 0.f;
        __syncthreads();
        int sh = lvl * 8;
        for (int c = t; c < C_; c += T) {
            float e = se[c];
            if (e > 0.f) {
                unsigned k = __float_as_uint(e);
                bool match = (((unsigned long long)k >> (sh + 8)) ==
                              ((unsigned long long)pref >> (sh + 8)));
                if (match) atomicAdd(&binM[(k >> sh) & 0xFFu], e);
            }
        }
        __syncthreads();
        if (t == 0) {
            float run = gAb; int sel = -1; float selRun = gAb;
            int lastnz = -1; float lastRun = gAb;
            for (int bi = 255; bi >= 0; bi--) {
                float bm = binM[bi];
                if (bm > 0.f && run + bm >= target) { sel = bi; selRun = run; break; }
                if (bm > 0.f) { lastnz = bi; lastRun = run; }
                run += bm;
            }
            if (sel < 0) { sel = lastnz; selRun = lastRun; }
            sh_pref = pref | ((unsigned)sel << sh);
            sh_gAbove = selRun;
        }
        __syncthreads();
        pref = sh_pref; gAb = sh_gAbove;
        __syncthreads();
    }
    float v = __uint_as_float(pref);
    float i0f = ceilf((target - gAb) / v);
    float thr;
    if (i0f >= 2.0f || gAb <= 0.f) {
        thr = v;
    } else {
        unsigned pk = 0xFFFFFFFFu;
        for (int c = t; c < C_; c += T) {
            float e = se[c];
            if (e > v) { unsigned k = __float_as_uint(e); if (k < pk) pk = k; }
        }
        unsigned* redu = (unsigned*)red;
        redu[t] = pk; __syncthreads();
        for (int o = 256; o > 0; o >>= 1) {
            if (t < o) { unsigned a = redu[t], q = redu[t + o]; redu[t] = (a < q) ? a : q; }
            __syncthreads();
        }
        unsigned pm = redu[0];
        float pred = (pm == 0xFFFFFFFFu) ? v : __uint_as_float(pm);
        float d1 = target - gAb;
        float d2 = gAb + v - target;
        thr = (d1 <= d2) ? pred : v;
        __syncthreads();
    }

    float ks = 0.f;
    for (int c = t; c < C_; c += T) { float e = se[c]; if (e >= thr) ks += e; }
    red[t] = ks; __syncthreads();
    for (int o = 256; o > 0; o >>= 1) { if (t < o) red[t] += red[t + o]; __syncthreads(); }
    if (t == 0) {
        float et = sh_et;
        float denom = et + red[0] + EPS_;
        float p = et / denom;
        g_loss[b] = -logf(p + EPS_);
    }
}

// -------- 8) final mean --------
__global__ void k_final(float* out) {
    __shared__ float red[256];
    int t = threadIdx.x;
    red[t] = g_loss[t]; __syncthreads();
    for (int o = 128; o > 0; o >>= 1) { if (t < o) red[t] += red[t + o]; __syncthreads(); }
    if (t == 0) out[0] = red[0] * (1.0f / (float)B_);
}

extern "C" void kernel_launch(void* const* d_in, const int* in_sizes, int n_in,
                              void* d_out, int out_size) {
    (void)in_sizes; (void)n_in; (void)out_size;
    const float* results  = (const float*)d_in[0];
    const float* features = (const float*)d_in[1];
    const int*   indexes  = (const int*)d_in[2];
    const int*   labels   = (const int*)d_in[3];
    float* out = (float*)d_out;

    k_norm    <<<B_, 256>>>(results);
    k_zero    <<<C_ / 256, 256>>>();
    k_hist    <<<N_ / 256, 256>>>(labels);
    k_scan    <<<1, 256>>>();
    k_scatter <<<N_ / 256, 256>>>(labels);
    k_agg     <<<C_, 256>>>(features);
    k_gemm_mma<<<128, 256>>>();
    k_focal   <<<B_, 512>>>(labels, indexes);
    k_final   <<<1, 256>>>(out);
}

// round 6
// speedup vs baseline: 1.9955x; 1.4022x over previous
#include <cuda_runtime.h>
#include <cuda_bf16.h>
#include <math.h>
#include <stdint.h>

#define B_    256
#define D_    1024
#define N_    65536
#define C_    8192
#define TEMP_ 0.05f
#define TOPP_ 0.1f
#define EPS_  1e-6f

// -------- scratch (device globals: no allocation allowed) --------
__device__ __nv_bfloat16 g_A2[(size_t)B_ * 2048];   // [b][k]: 0..1023 hi, 1024..2047 lo (1 MB)
__device__ __nv_bfloat16 g_B2[(size_t)C_ * 2048];   // [c][k]: hi | lo (32 MB)
__device__ int   g_counts[C_];
__device__ int   g_offsets[C_];
__device__ int   g_cursor[C_];
__device__ int   g_order[N_];
__device__ float g_sim[(size_t)B_ * C_];            // logits (8 MB)
__device__ float g_loss[B_];

__device__ __forceinline__ uint32_t smem_u32(const void* p) {
    uint32_t a;
    asm("{ .reg .u64 t; cvta.to.shared.u64 t, %1; cvt.u32.u64 %0, t; }" : "=r"(a) : "l"(p));
    return a;
}
__device__ __forceinline__ uint32_t swz128(uint32_t o) { return o ^ ((o >> 3) & 0x70u); }

// -------- 1) L2-normalize queries (+fused counts zeroing), bf16 hi/lo split --------
__global__ void k_norm(const float* __restrict__ res) {
    __shared__ float red[256];
    int b = blockIdx.x, t = threadIdx.x;
    if (b < 32) g_counts[b * 256 + t] = 0;          // fused k_zero
    const float* row = res + (size_t)b * D_;
    float s = 0.f;
    for (int i = t; i < D_; i += 256) { float v = row[i]; s += v * v; }
    red[t] = s; __syncthreads();
    for (int o = 128; o > 0; o >>= 1) { if (t < o) red[t] += red[t + o]; __syncthreads(); }
    float inv = rsqrtf(red[0]);
    for (int i = t; i < D_; i += 256) {
        float v = row[i] * inv;
        __nv_bfloat16 hi = __float2bfloat16_rn(v);
        __nv_bfloat16 lo = __float2bfloat16_rn(v - __bfloat162float(hi));
        g_A2[(size_t)b * 2048 + i]        = hi;
        g_A2[(size_t)b * 2048 + 1024 + i] = lo;
    }
}

// -------- 2) histogram of labels --------
__global__ void k_hist(const int* __restrict__ labels) {
    int n = blockIdx.x * blockDim.x + threadIdx.x;
    if (n < N_) atomicAdd(&g_counts[labels[n]], 1);
}

// -------- 3) exclusive scan of counts: 1024 thr x 8 regs + warp scan --------
__global__ void __launch_bounds__(1024) k_scan() {
    __shared__ int wtot[32];
    int t = threadIdx.x, lane = t & 31, w = t >> 5;
    int base = t * 8;
    int v[8]; int tot = 0;
#pragma unroll
    for (int i = 0; i < 8; i++) { v[i] = g_counts[base + i]; tot += v[i]; }
    int inc = tot;
#pragma unroll
    for (int o = 1; o < 32; o <<= 1) {
        int x = __shfl_up_sync(0xFFFFFFFFu, inc, o);
        if (lane >= o) inc += x;
    }
    if (lane == 31) wtot[w] = inc;
    __syncthreads();
    if (w == 0) {
        int x = wtot[lane];
        int y = x;
#pragma unroll
        for (int o = 1; o < 32; o <<= 1) {
            int z = __shfl_up_sync(0xFFFFFFFFu, y, o);
            if (lane >= o) y += z;
        }
        wtot[lane] = y - x;   // exclusive
    }
    __syncthreads();
    int excl = wtot[w] + inc - tot;
#pragma unroll
    for (int i = 0; i < 8; i++) {
        g_offsets[base + i] = excl;
        g_cursor[base + i]  = excl;
        excl += v[i];
    }
}

// -------- 4) counting-sort scatter --------
__global__ void k_scatter(const int* __restrict__ labels) {
    int n = blockIdx.x * blockDim.x + threadIdx.x;
    if (n < N_) {
        int l = labels[n];
        int p = atomicAdd(&g_cursor[l], 1);
        g_order[p] = n;
    }
}

// -------- 5) per-cluster mean/TEMP, bf16 hi/lo split --------
__global__ void k_agg(const float* __restrict__ feat) {
    __shared__ int idxs[64];
    int c = blockIdx.x, t = threadIdx.x;
    int cnt = g_counts[c], off = g_offsets[c];
    float4 acc = make_float4(0.f, 0.f, 0.f, 0.f);
    for (int s0 = 0; s0 < cnt; s0 += 64) {
        int m = cnt - s0; if (m > 64) m = 64;
        if (t < m) idxs[t] = g_order[off + s0 + t];
        __syncthreads();
        for (int i = 0; i < m; i++) {
            const float4 v = *((const float4*)(feat + (size_t)idxs[i] * D_) + t);
            acc.x += v.x; acc.y += v.y; acc.z += v.z; acc.w += v.w;
        }
        __syncthreads();
    }
    float sc = (cnt > 0) ? 1.0f / (TEMP_ * (float)cnt) : 0.f;
    float r0 = acc.x * sc, r1 = acc.y * sc, r2 = acc.z * sc, r3 = acc.w * sc;
    __nv_bfloat16 h0 = __float2bfloat16_rn(r0), h1 = __float2bfloat16_rn(r1);
    __nv_bfloat16 h2 = __float2bfloat16_rn(r2), h3 = __float2bfloat16_rn(r3);
    __nv_bfloat16 l0 = __float2bfloat16_rn(r0 - __bfloat162float(h0));
    __nv_bfloat16 l1 = __float2bfloat16_rn(r1 - __bfloat162float(h1));
    __nv_bfloat16 l2 = __float2bfloat16_rn(r2 - __bfloat162float(h2));
    __nv_bfloat16 l3 = __float2bfloat16_rn(r3 - __bfloat162float(h3));
    __nv_bfloat16* rowp = g_B2 + (size_t)c * 2048;
    __nv_bfloat162 hA; hA.x = h0; hA.y = h1;
    __nv_bfloat162 hB; hB.x = h2; hB.y = h3;
    __nv_bfloat162 lA; lA.x = l0; lA.y = l1;
    __nv_bfloat162 lB; lB.x = l2; lB.y = l3;
    *(__nv_bfloat162*)(rowp + 4 * t)            = hA;
    *(__nv_bfloat162*)(rowp + 4 * t + 2)        = hB;
    *(__nv_bfloat162*)(rowp + 1024 + 4 * t)     = lA;
    *(__nv_bfloat162*)(rowp + 1024 + 4 * t + 2) = lB;
}

// -------- 6) GEMM: sim = A2 @ B2^T via mma.sync bf16, double-buffered smem --------
__global__ void __launch_bounds__(256, 1) k_gemm_mma() {
    __shared__ __align__(1024) __nv_bfloat16 shA[2][128 * 64];  // 2 x 16 KB
    __shared__ __align__(1024) __nv_bfloat16 shB[2][128 * 64];  // 2 x 16 KB
    uint32_t sA0 = smem_u32(shA[0]), sB0 = smem_u32(shB[0]);
    int tid = threadIdx.x, wid = tid >> 5, l = tid & 31;
    int nt = blockIdx.x & 63, mt = blockIdx.x >> 6;
    int b0 = mt * 128, c0 = nt * 128;
    int mw = wid >> 1, nw = wid & 1;            // warp grid 4x2

    float acc[2][8][4];
#pragma unroll
    for (int mi = 0; mi < 2; mi++)
#pragma unroll
        for (int ni = 0; ni < 8; ni++)
#pragma unroll
            for (int r = 0; r < 4; r++) acc[mi][ni][r] = 0.f;

    int ur = tid >> 3, usg = tid & 7;
    uint32_t so[4];
#pragma unroll
    for (int i = 0; i < 4; i++) so[i] = swz128((uint32_t)((ur + i * 32) * 128 + usg * 16));

    uint4 pa[4], pb[4];
    {   // preload + store chunk 0 into buffer 0
        const uint4* gA = (const uint4*)(g_A2 + (size_t)b0 * 2048);
        const uint4* gB = (const uint4*)(g_B2 + (size_t)c0 * 2048);
#pragma unroll
        for (int i = 0; i < 4; i++) {
            pa[i] = gA[(size_t)(ur + i * 32) * 256 + usg];
            pb[i] = gB[(size_t)(ur + i * 32) * 256 + usg];
        }
#pragma unroll
        for (int i = 0; i < 4; i++) {
            asm volatile("st.shared.v4.b32 [%0], {%1, %2, %3, %4};"
                         :: "r"(sA0 + so[i]), "r"(pa[i].x), "r"(pa[i].y), "r"(pa[i].z), "r"(pa[i].w) : "memory");
            asm volatile("st.shared.v4.b32 [%0], {%1, %2, %3, %4};"
                         :: "r"(sB0 + so[i]), "r"(pb[i].x), "r"(pb[i].y), "r"(pb[i].z), "r"(pb[i].w) : "memory");
        }
    }

    for (int vc = 0; vc < 48; vc++) {
        __syncthreads();
        int s = vc & 1;
        uint32_t sAc = sA0 + s * 16384, sBc = sB0 + s * 16384;

        if (vc < 47) {   // issue LDG for chunk vc+1 (hidden behind MMA below)
            int v2 = vc + 1;
            int ka = (v2 < 32) ? v2 : v2 - 32;   // A: hi 0..15 | lo 16..31
            int kb = (v2 < 16) ? v2 : v2 - 16;   // B: hi 0..15 | lo 16..31
            const uint4* gA = (const uint4*)(g_A2 + (size_t)b0 * 2048 + ka * 64);
            const uint4* gB = (const uint4*)(g_B2 + (size_t)c0 * 2048 + kb * 64);
#pragma unroll
            for (int i = 0; i < 4; i++) {
                pa[i] = gA[(size_t)(ur + i * 32) * 256 + usg];
                pb[i] = gB[(size_t)(ur + i * 32) * 256 + usg];
            }
        }

#pragma unroll
        for (int kk = 0; kk < 4; kk++) {
            uint32_t a[2][4];
#pragma unroll
            for (int mi = 0; mi < 2; mi++) {
                uint32_t row = mw * 32 + mi * 16 + (l & 15);
                uint32_t addr = sAc + swz128(row * 128 + kk * 32 + ((l >> 4) & 1) * 16);
                asm volatile("ldmatrix.sync.aligned.m8n8.x4.shared.b16 {%0,%1,%2,%3}, [%4];"
                             : "=r"(a[mi][0]), "=r"(a[mi][1]), "=r"(a[mi][2]), "=r"(a[mi][3])
                             : "r"(addr));
            }
            uint32_t bfr[8][2];
#pragma unroll
            for (int ni = 0; ni < 8; ni++) {
                uint32_t row = nw * 64 + ni * 8 + (l & 7);
                uint32_t addr = sBc + swz128(row * 128 + kk * 32 + ((l >> 3) & 1) * 16);
                asm volatile("ldmatrix.sync.aligned.m8n8.x2.shared.b16 {%0,%1}, [%2];"
                             : "=r"(bfr[ni][0]), "=r"(bfr[ni][1]) : "r"(addr));
            }
#pragma unroll
            for (int mi = 0; mi < 2; mi++)
#pragma unroll
                for (int ni = 0; ni < 8; ni++)
                    asm volatile(
                        "mma.sync.aligned.m16n8k16.row.col.f32.bf16.bf16.f32 "
                        "{%0,%1,%2,%3}, {%4,%5,%6,%7}, {%8,%9}, {%0,%1,%2,%3};"
                        : "+f"(acc[mi][ni][0]), "+f"(acc[mi][ni][1]),
                          "+f"(acc[mi][ni][2]), "+f"(acc[mi][ni][3])
                        : "r"(a[mi][0]), "r"(a[mi][1]), "r"(a[mi][2]), "r"(a[mi][3]),
                          "r"(bfr[ni][0]), "r"(bfr[ni][1]));
        }

        if (vc < 47) {   // store chunk vc+1 into the other buffer (no extra sync needed)
            uint32_t dA = sA0 + (s ^ 1) * 16384, dB = sB0 + (s ^ 1) * 16384;
#pragma unroll
            for (int i = 0; i < 4; i++) {
                asm volatile("st.shared.v4.b32 [%0], {%1, %2, %3, %4};"
                             :: "r"(dA + so[i]), "r"(pa[i].x), "r"(pa[i].y), "r"(pa[i].z), "r"(pa[i].w) : "memory");
                asm volatile("st.shared.v4.b32 [%0], {%1, %2, %3, %4};"
                             :: "r"(dB + so[i]), "r"(pb[i].x), "r"(pb[i].y), "r"(pb[i].z), "r"(pb[i].w) : "memory");
            }
        }
    }

    int gr = l >> 2, gc = (l & 3) * 2;
#pragma unroll
    for (int mi = 0; mi < 2; mi++) {
        int row = b0 + mw * 32 + mi * 16 + gr;
#pragma unroll
        for (int ni = 0; ni < 8; ni++) {
            int col = c0 + nw * 64 + ni * 8 + gc;
            float2 v0; v0.x = acc[mi][ni][0]; v0.y = acc[mi][ni][1];
            float2 v1; v1.x = acc[mi][ni][2]; v1.y = acc[mi][ni][3];
            *(float2*)&g_sim[(size_t)row * C_ + col]       = v0;
            *(float2*)&g_sim[(size_t)(row + 8) * C_ + col] = v1;
        }
    }
}

// -------- 7) focal masked softmax: radix-select, parallel bin machinery --------
__global__ void __launch_bounds__(1024) k_focal(const int* __restrict__ labels,
                                                const int* __restrict__ indexes) {
    __shared__ float se[C_];          // masked exps, target zeroed (32 KB)
    __shared__ float red[1024];
    __shared__ float binP[4][256];    // privatized histogram (4 KB)
    __shared__ float binM[256];
    __shared__ float suf[256];
    __shared__ int   redi[1024];
    __shared__ float sh_et;
    __shared__ unsigned sh_pref;
    __shared__ float sh_gAbove;
    const int T = 1024;
    int b = blockIdx.x, t = threadIdx.x;
    int pcopy = (t >> 8) & 3;         // warp-group private copy
    int tgt = labels[indexes[b]];

    float ls = 0.f;
#pragma unroll
    for (int i = 0; i < 8; i++) {
        int c = t + i * T;
        float e = 0.f;
        if (g_counts[c] > 0) e = __expf(g_sim[(size_t)b * C_ + c]);
        if (c == tgt) { sh_et = e; e = 0.f; }
        se[c] = e; ls += e;
    }
    red[t] = ls; __syncthreads();
    for (int o = 512; o > 0; o >>= 1) { if (t < o) red[t] += red[t + o]; __syncthreads(); }
    float S = red[0];
    float target = TOPP_ * S;

    unsigned pref = 0; float gAb = 0.f;
    for (int lvl = 3; lvl >= 0; lvl--) {
        // zero private bins
        ((float*)binP)[t] = 0.f;
        __syncthreads();
        int sh = lvl * 8;
#pragma unroll
        for (int i = 0; i < 8; i++) {
            float e = se[t + i * T];
            if (e > 0.f) {
                unsigned k = __float_as_uint(e);
                bool match = (((unsigned long long)k >> (sh + 8)) ==
                              ((unsigned long long)pref >> (sh + 8)));
                if (match) atomicAdd(&binP[pcopy][(k >> sh) & 0xFFu], e);
            }
        }
        __syncthreads();
        // merge privatized copies + init suffix array
        if (t < 256) {
            float m = binP[0][t] + binP[1][t] + binP[2][t] + binP[3][t];
            binM[t] = m; suf[t] = m;
        }
        __syncthreads();
        // parallel suffix sum over 256 bins
        for (int o = 1; o < 256; o <<= 1) {
            float x = (t < 256 && t + o < 256) ? suf[t + o] : 0.f;
            __syncthreads();
            if (t < 256) suf[t] += x;
            __syncthreads();
        }
        // selection: highest bin with mass>0 and gAb+suf >= target; fallback lowest nonzero
        int cand = -1, nz = 256;
        if (t < 256) {
            float bm = binM[t];
            if (bm > 0.f) {
                nz = t;
                if (gAb + suf[t] >= target) cand = t;
            }
        }
        redi[t] = cand; __syncthreads();
        for (int o = 512; o > 0; o >>= 1) {
            if (t < o) { int x = redi[t + o]; if (x > redi[t]) redi[t] = x; }
            __syncthreads();
        }
        int candMax = redi[0]; __syncthreads();
        redi[t] = nz; __syncthreads();
        for (int o = 512; o > 0; o >>= 1) {
            if (t < o) { int x = redi[t + o]; if (x < redi[t]) redi[t] = x; }
            __syncthreads();
        }
        int nzMin = redi[0];
        if (t == 0) {
            int sel = (candMax >= 0) ? candMax : ((nzMin < 256) ? nzMin : 0);
            sh_pref = pref | ((unsigned)sel << sh);
            sh_gAbove = gAb + suf[sel] - binM[sel];
        }
        __syncthreads();
        pref = sh_pref; gAb = sh_gAbove;
        __syncthreads();
    }
    float v = __uint_as_float(pref);
    float i0f = ceilf((target - gAb) / v);
    float thr;
    if (i0f >= 2.0f || gAb <= 0.f) {
        thr = v;
    } else {
        // predecessor: min element strictly above v
        unsigned pk = 0xFFFFFFFFu;
#pragma unroll
        for (int i = 0; i < 8; i++) {
            float e = se[t + i * T];
            if (e > v) { unsigned k = __float_as_uint(e); if (k < pk) pk = k; }
        }
        unsigned* redu = (unsigned*)redi;
        redu[t] = pk; __syncthreads();
        for (int o = 512; o > 0; o >>= 1) {
            if (t < o) { unsigned a = redu[t], q = redu[t + o]; redu[t] = (a < q) ? a : q; }
            __syncthreads();
        }
        unsigned pm = redu[0];
        float pred = (pm == 0xFFFFFFFFu) ? v : __uint_as_float(pm);
        float d1 = target - gAb;
        float d2 = gAb + v - target;
        thr = (d1 <= d2) ? pred : v;
        __syncthreads();
    }

    float ks = 0.f;
#pragma unroll
    for (int i = 0; i < 8; i++) { float e = se[t + i * T]; if (e >= thr) ks += e; }
    red[t] = ks; __syncthreads();
    for (int o = 512; o > 0; o >>= 1) { if (t < o) red[t] += red[t + o]; __syncthreads(); }
    if (t == 0) {
        float et = sh_et;
        float denom = et + red[0] + EPS_;
        float p = et / denom;
        g_loss[b] = -logf(p + EPS_);
    }
}

// -------- 8) final mean --------
__global__ void k_final(float* out) {
    __shared__ float red[256];
    int t = threadIdx.x;
    red[t] = g_loss[t]; __syncthreads();
    for (int o = 128; o > 0; o >>= 1) { if (t < o) red[t] += red[t + o]; __syncthreads(); }
    if (t == 0) out[0] = red[0] * (1.0f / (float)B_);
}

extern "C" void kernel_launch(void* const* d_in, const int* in_sizes, int n_in,
                              void* d_out, int out_size) {
    (void)in_sizes; (void)n_in; (void)out_size;
    const float* results  = (const float*)d_in[0];
    const float* features = (const float*)d_in[1];
    const int*   indexes  = (const int*)d_in[2];
    const int*   labels   = (const int*)d_in[3];
    float* out = (float*)d_out;

    k_norm    <<<B_, 256>>>(results);        // also zeroes g_counts
    k_hist    <<<N_ / 256, 256>>>(labels);
    k_scan    <<<1, 1024>>>();
    k_scatter <<<N_ / 256, 256>>>(labels);
    k_agg     <<<C_, 256>>>(features);
    k_gemm_mma<<<128, 256>>>();
    k_focal   <<<B_, 1024>>>(labels, indexes);
    k_final   <<<1, 256>>>(out);
}